// round 15
// baseline (speedup 1.0000x reference)
#include <cuda_runtime.h>
#include <cuda_fp16.h>
#include <cstdint>

#define D_ 128
#define TM 224
#define NTH 448
#define XSCALE 1024.0f
#define WSCALE 256.0f
#define INV_SC 3.814697265625e-06f   // 2^-18

// smem layout (bytes) — x never touches smem
#define WB 36992                      // 136 n-rows * 272 B
#define OFF_W1 0
#define OFF_W2 WB
#define OFF_SB  (2*WB)                // 73984
#define OFF_SG  (OFF_SB + 512)
#define OFF_SBE (OFF_SG + 512)
#define OFF_GBE (OFF_SBE + 512)       // 64 float4: {g[2i],g[2i+1],be[2i],be[2i+1]}
#define OFF_SCB (OFF_GBE + 1024)      // 8 * 132 * 4 = 4224
#define OFF_GK  (OFF_SCB + 4224)
#define OFF_BBK (OFF_GK + 32)
#define OFF_BDK (OFF_BBK + 32)
#define OFF_SCI (OFF_BDK + 32)
#define SMEM_TOTAL (OFF_SCI + 32)

__device__ __forceinline__ uint32_t s2u(const void* p) {
    uint32_t a;
    asm("{ .reg .u64 t; cvta.to.shared.u64 t, %1; cvt.u32.u64 %0, t; }" : "=r"(a) : "l"(p));
    return a;
}
__device__ __forceinline__ uint32_t f2h2(float lo, float hi) {
    uint32_t d;
    asm("cvt.rn.f16x2.f32 %0, %1, %2;" : "=r"(d) : "f"(hi), "f"(lo));
    return d;
}
__device__ __forceinline__ float2 h2f2(uint32_t h) {
    float2 r;
    asm("{ .reg .b16 l, hh; mov.b32 {l, hh}, %2; cvt.f32.f16 %0, l; cvt.f32.f16 %1, hh; }"
        : "=f"(r.x), "=f"(r.y) : "r"(h));
    return r;
}
__device__ __forceinline__ void split2(float a, float b, uint32_t& hi, uint32_t& lo) {
    hi = f2h2(a, b);
    float2 f = h2f2(hi);
    lo = f2h2(a - f.x, b - f.y);
}
__device__ __forceinline__ void ldmx4(uint32_t* r, uint32_t addr) {
    asm volatile("ldmatrix.sync.aligned.m8n8.x4.shared.b16 {%0,%1,%2,%3}, [%4];"
                 : "=r"(r[0]), "=r"(r[1]), "=r"(r[2]), "=r"(r[3]) : "r"(addr));
}
__device__ __forceinline__ void mma16816(float4& c, const uint32_t* a, uint32_t b0, uint32_t b1) {
    asm volatile("mma.sync.aligned.m16n8k16.row.col.f32.f16.f16.f32 "
                 "{%0,%1,%2,%3},{%4,%5,%6,%7},{%8,%9},{%0,%1,%2,%3};"
                 : "+f"(c.x), "+f"(c.y), "+f"(c.z), "+f"(c.w)
                 : "r"(a[0]), "r"(a[1]), "r"(a[2]), "r"(a[3]), "r"(b0), "r"(b1));
}

__global__ void __launch_bounds__(NTH, 1)
l1q_mma(const float* __restrict__ x, const float* __restrict__ W,
        const float* __restrict__ bias, const float* __restrict__ gamma,
        const float* __restrict__ beta, const float* __restrict__ cb,
        float* __restrict__ o_idx, float* __restrict__ o_soft,
        float* __restrict__ o_emb, float* __restrict__ o_log,
        int B, int NT, int grid)
{
    extern __shared__ char sm[];
    const uint32_t base = s2u(sm);
    const int tid = threadIdx.x;
    const int lane = tid & 31;
    const int warp = tid >> 5;

    float* sb  = (float*)(sm + OFF_SB);
    float* sg  = (float*)(sm + OFF_SG);
    float* sbe = (float*)(sm + OFF_SBE);
    float* scb = (float*)(sm + OFF_SCB);
    float* gk  = (float*)(sm + OFF_GK);
    float* bbk = (float*)(sm + OFF_BBK);
    float* bdk = (float*)(sm + OFF_BDK);
    float* sci = (float*)(sm + OFF_SCI);

    // ---- stage W (scaled x256, fp16 hi/lo split) as [n][k], stride 272 B ----
    #pragma unroll 1
    for (int q2 = tid; q2 < 8192; q2 += NTH) {
        int n = q2 >> 6, kp = q2 & 63;
        float2 v = *(const float2*)&W[(size_t)n * 128 + 2 * kp];
        v.x *= WSCALE; v.y *= WSCALE;
        uint32_t hi, lo; split2(v.x, v.y, hi, lo);
        uint32_t off = (uint32_t)n * 272 + (uint32_t)kp * 4;
        *(uint32_t*)(sm + OFF_W1 + off) = hi;
        *(uint32_t*)(sm + OFF_W2 + off) = lo;
    }
    if (tid < 128) { sb[tid] = bias[tid]; sg[tid] = gamma[tid]; sbe[tid] = beta[tid]; }
    #pragma unroll 1
    for (int i = tid; i < 1024; i += NTH) { int k = i >> 7, j = i & 127; scb[k * 132 + j] = cb[i]; }
    __syncthreads();
    if (tid < 64) {
        float4 gb;
        gb.x = sg[2 * tid]; gb.y = sg[2 * tid + 1];
        gb.z = sbe[2 * tid]; gb.w = sbe[2 * tid + 1];
        *(float4*)(sm + OFF_GBE + tid * 16) = gb;
    }

    // ---- ck'' = W^T (gamma o c_k) appended as B-rows 128..135 ----
    if (tid < 128) {
        int d = tid;
        float a8[8] = {0, 0, 0, 0, 0, 0, 0, 0};
        #pragma unroll 4
        for (int j = 0; j < 128; j++) {
            float tj = W[(size_t)j * 128 + d] * sg[j];
            #pragma unroll
            for (int k = 0; k < 8; k++) a8[k] = fmaf(tj, scb[k * 132 + j], a8[k]);
        }
        #pragma unroll
        for (int k = 0; k < 8; k++) {
            float vs = a8[k] * WSCALE;
            __half h1 = __float2half_rn(vs);
            __half h2 = __float2half_rn(vs - __half2float(h1));
            uint32_t off = (uint32_t)(128 + k) * 272 + (uint32_t)d * 2;
            *(__half*)(sm + OFF_W1 + off) = h1;
            *(__half*)(sm + OFF_W2 + off) = h2;
        }
    }
    if (tid < 8) {
        int k = tid; float g = 0, bb = 0, bd = 0, s2 = 0;
        for (int j = 0; j < 128; j++) {
            float c = scb[k * 132 + j], gj = sg[j];
            g  = fmaf(gj, c, g);
            bb = fmaf(sbe[j], c, bb);
            bd = fmaf(sb[j] * gj, c, bd);
            s2 = fmaf(c, c, s2);
        }
        gk[k] = g; bbk[k] = bb; bdk[k] = bd;
        sci[k] = 1.0f / fmaxf(sqrtf(s2), 1e-12f);
    }
    __syncthreads();
    // From here: smem is read-only; no block barriers in the main loop.

    const int g4 = lane >> 2, c4l = lane & 3;
    const uint32_t boff = (uint32_t)(lane & 7) * 272 + (uint32_t)(lane >> 3) * 16;
    const int rbase = warp * 16 + g4;

    // raw x fragment staging (global -> regs, single-buffer, distance-1 prefetch)
    float2 P[8];
    auto ldkp = [&](const float* p0, const float* p1, int kp) {
        int b0 = kp * 32 + 2 * c4l;
        P[0] = *(const float2*)(p0 + b0);
        P[1] = *(const float2*)(p1 + b0);
        P[2] = *(const float2*)(p0 + b0 + 8);
        P[3] = *(const float2*)(p1 + b0 + 8);
        P[4] = *(const float2*)(p0 + b0 + 16);
        P[5] = *(const float2*)(p1 + b0 + 16);
        P[6] = *(const float2*)(p0 + b0 + 24);
        P[7] = *(const float2*)(p1 + b0 + 24);
    };
    auto rowptr = [&](int t_, int add) -> const float* {
        long r = (long)t_ * TM + rbase + add;
        if (r > (long)B - 1) r = B - 1;
        return x + (size_t)r * D_;
    };

    int t0 = blockIdx.x;
    const float* pr0 = rowptr(t0 < NT ? t0 : 0, 0);
    const float* pr1 = rowptr(t0 < NT ? t0 : 0, 8);
    if (t0 < NT) ldkp(pr0, pr1, 0);

    for (int t = t0; t < NT; t += grid) {
        int tn = t + grid;
        const float* nr0 = (tn < NT) ? rowptr(tn, 0) : pr0;
        const float* nr1 = (tn < NT) ? rowptr(tn, 8) : pr1;

        // ---- MMA: warp's 16 rows x N=136 (17 n-tiles), K=128, 3 passes ----
        float4 acc[17];
        #pragma unroll
        for (int j = 0; j < 17; j++) acc[j] = make_float4(0.f, 0.f, 0.f, 0.f);

        #pragma unroll
        for (int kp = 0; kp < 4; kp++) {
            uint32_t ah[2][4], al[2][4];
            #pragma unroll
            for (int kk = 0; kk < 2; kk++)
                #pragma unroll
                for (int v = 0; v < 4; v++)
                    split2(P[kk * 4 + v].x * XSCALE, P[kk * 4 + v].y * XSCALE,
                           ah[kk][v], al[kk][v]);
            // prefetch next kp of this tile, or kp0 of next tile
            if (kp < 3) ldkp(pr0, pr1, kp + 1);
            else        ldkp(nr0, nr1, 0);

            uint32_t wk = base + boff + (uint32_t)kp * 64;
            // software-pipelined B fragments: two buffers, no copies
            uint32_t Bc[4][4], Bn[4][4];   // [bh0, bh1, bl0, bl1][4]

            ldmx4(Bc[0], wk + 0u * 2176 + OFF_W1);
            ldmx4(Bc[1], wk + 1u * 2176 + OFF_W1);
            ldmx4(Bc[2], wk + 0u * 2176 + OFF_W2);
            ldmx4(Bc[3], wk + 1u * 2176 + OFF_W2);

            #pragma unroll
            for (int jph = 0; jph < 4; jph++) {
                // even slot jp = 2*jph : frags in Bc, prefetch jp+1 into Bn
                {
                    int j0 = 4 * jph, j1 = 4 * jph + 1;
                    uint32_t wn0 = wk + (uint32_t)(4 * jph + 2) * 2176;
                    uint32_t wn1 = wk + (uint32_t)(4 * jph + 3) * 2176;
                    ldmx4(Bn[0], wn0 + OFF_W1);
                    ldmx4(Bn[1], wn1 + OFF_W1);
                    ldmx4(Bn[2], wn0 + OFF_W2);
                    ldmx4(Bn[3], wn1 + OFF_W2);
                    mma16816(acc[j0], ah[0], Bc[0][0], Bc[0][1]);
                    mma16816(acc[j1], ah[0], Bc[1][0], Bc[1][1]);
                    mma16816(acc[j0], ah[0], Bc[2][0], Bc[2][1]);
                    mma16816(acc[j1], ah[0], Bc[3][0], Bc[3][1]);
                    mma16816(acc[j0], al[0], Bc[0][0], Bc[0][1]);
                    mma16816(acc[j1], al[0], Bc[1][0], Bc[1][1]);
                    mma16816(acc[j0], ah[1], Bc[0][2], Bc[0][3]);
                    mma16816(acc[j1], ah[1], Bc[1][2], Bc[1][3]);
                    mma16816(acc[j0], ah[1], Bc[2][2], Bc[2][3]);
                    mma16816(acc[j1], ah[1], Bc[3][2], Bc[3][3]);
                    mma16816(acc[j0], al[1], Bc[0][2], Bc[0][3]);
                    mma16816(acc[j1], al[1], Bc[1][2], Bc[1][3]);
                }
                // odd slot jp = 2*jph+1 : frags in Bn, prefetch jp+2 into Bc
                {
                    int j0 = 4 * jph + 2, j1 = 4 * jph + 3;
                    if (jph < 3) {
                        uint32_t wn0 = wk + (uint32_t)(4 * jph + 4) * 2176;
                        uint32_t wn1 = wk + (uint32_t)(4 * jph + 5) * 2176;
                        ldmx4(Bc[0], wn0 + OFF_W1);
                        ldmx4(Bc[1], wn1 + OFF_W1);
                        ldmx4(Bc[2], wn0 + OFF_W2);
                        ldmx4(Bc[3], wn1 + OFF_W2);
                    } else {
                        uint32_t wn = wk + 16u * 2176;
                        ldmx4(Bc[0], wn + OFF_W1);
                        ldmx4(Bc[2], wn + OFF_W2);
                    }
                    mma16816(acc[j0], ah[0], Bn[0][0], Bn[0][1]);
                    mma16816(acc[j1], ah[0], Bn[1][0], Bn[1][1]);
                    mma16816(acc[j0], ah[0], Bn[2][0], Bn[2][1]);
                    mma16816(acc[j1], ah[0], Bn[3][0], Bn[3][1]);
                    mma16816(acc[j0], al[0], Bn[0][0], Bn[0][1]);
                    mma16816(acc[j1], al[0], Bn[1][0], Bn[1][1]);
                    mma16816(acc[j0], ah[1], Bn[0][2], Bn[0][3]);
                    mma16816(acc[j1], ah[1], Bn[1][2], Bn[1][3]);
                    mma16816(acc[j0], ah[1], Bn[2][2], Bn[2][3]);
                    mma16816(acc[j1], ah[1], Bn[3][2], Bn[3][3]);
                    mma16816(acc[j0], al[1], Bn[0][2], Bn[0][3]);
                    mma16816(acc[j1], al[1], Bn[1][2], Bn[1][3]);
                }
            }
            // j = 16 singleton (logits columns) — frags prefetched into Bc
            mma16816(acc[16], ah[0], Bc[0][0], Bc[0][1]);
            mma16816(acc[16], ah[0], Bc[2][0], Bc[2][1]);
            mma16816(acc[16], al[0], Bc[0][0], Bc[0][1]);
            mma16816(acc[16], ah[1], Bc[0][2], Bc[0][3]);
            mma16816(acc[16], ah[1], Bc[2][2], Bc[2][3]);
            mma16816(acc[16], al[1], Bc[0][2], Bc[0][3]);
        }
        pr0 = nr0; pr1 = nr1;

        // ---- fused epilogue: both half-rows together, h overwrites acc ----
        float s1a = 0.f, s2a = 0.f, s1b = 0.f, s2b = 0.f;
        #pragma unroll
        for (int j = 0; j < 16; j++) {
            float2 bb = *(const float2*)(sm + OFF_SB + (8 * j + 2 * c4l) * 4);
            float h0 = fmaf(acc[j].x, INV_SC, bb.x);
            float h1 = fmaf(acc[j].y, INV_SC, bb.y);
            float h2 = fmaf(acc[j].z, INV_SC, bb.x);
            float h3 = fmaf(acc[j].w, INV_SC, bb.y);
            acc[j] = make_float4(h0, h1, h2, h3);
            s1a += h0 + h1; s2a = fmaf(h0, h0, fmaf(h1, h1, s2a));
            s1b += h2 + h3; s2b = fmaf(h2, h2, fmaf(h3, h3, s2b));
        }
        s1a += __shfl_xor_sync(0xffffffffu, s1a, 1); s1a += __shfl_xor_sync(0xffffffffu, s1a, 2);
        s2a += __shfl_xor_sync(0xffffffffu, s2a, 1); s2a += __shfl_xor_sync(0xffffffffu, s2a, 2);
        s1b += __shfl_xor_sync(0xffffffffu, s1b, 1); s1b += __shfl_xor_sync(0xffffffffu, s1b, 2);
        s2b += __shfl_xor_sync(0xffffffffu, s2b, 1); s2b += __shfl_xor_sync(0xffffffffu, s2b, 2);
        float mua = s1a * 0.0078125f, mub = s1b * 0.0078125f;
        float rstda = rsqrtf(s2a * 0.0078125f - mua * mua + 1e-5f);
        float rstdb = rsqrtf(s2b * 0.0078125f - mub * mub + 1e-5f);

        float q2a = 0.f, q2b = 0.f;
        #pragma unroll
        for (int j = 0; j < 16; j++) {
            float4 gb = *(const float4*)(sm + OFF_GBE + (4 * j + c4l) * 16);
            float hn0 = fmaf((acc[j].x - mua) * rstda, gb.x, gb.z);
            float hn1 = fmaf((acc[j].y - mua) * rstda, gb.y, gb.w);
            float hn2 = fmaf((acc[j].z - mub) * rstdb, gb.x, gb.z);
            float hn3 = fmaf((acc[j].w - mub) * rstdb, gb.y, gb.w);
            q2a = fmaf(hn0, hn0, fmaf(hn1, hn1, q2a));
            q2b = fmaf(hn2, hn2, fmaf(hn3, hn3, q2b));
        }
        q2a += __shfl_xor_sync(0xffffffffu, q2a, 1); q2a += __shfl_xor_sync(0xffffffffu, q2a, 2);
        q2b += __shfl_xor_sync(0xffffffffu, q2b, 1); q2b += __shfl_xor_sync(0xffffffffu, q2b, 2);
        float invna = 1.0f / fmaxf(sqrtf(q2a), 1e-12f);
        float invnb = 1.0f / fmaxf(sqrtf(q2b), 1e-12f);

        float bd0 = bdk[2 * c4l], bd1 = bdk[2 * c4l + 1];
        float gk0 = gk[2 * c4l],  gk1 = gk[2 * c4l + 1];
        float bk0 = bbk[2 * c4l], bk1 = bbk[2 * c4l + 1];
        float sc0 = sci[2 * c4l], sc1 = sci[2 * c4l + 1];
        float l0a = fmaf(rstda, fmaf(acc[16].x, INV_SC, bd0) - mua * gk0, bk0) * invna * sc0;
        float l1a = fmaf(rstda, fmaf(acc[16].y, INV_SC, bd1) - mua * gk1, bk1) * invna * sc1;
        float l0b = fmaf(rstdb, fmaf(acc[16].z, INV_SC, bd0) - mub * gk0, bk0) * invnb * sc0;
        float l1b = fmaf(rstdb, fmaf(acc[16].w, INV_SC, bd1) - mub * gk1, bk1) * invnb * sc1;

        int bi2[2];
        #pragma unroll 1
        for (int hf = 0; hf < 2; hf++) {
            float l0 = hf ? l0b : l0a, l1 = hf ? l1b : l1a;
            int grow = t * TM + warp * 16 + hf * 8 + g4;

            float lg[8];
            #pragma unroll
            for (int kk = 0; kk < 8; kk++) {
                int src = (lane & ~3) | (kk >> 1);
                lg[kk] = __shfl_sync(0xffffffffu, (kk & 1) ? l1 : l0, src);
            }
            float mx = lg[0]; int bi = 0;
            #pragma unroll
            for (int kk = 1; kk < 8; kk++) if (lg[kk] > mx) { mx = lg[kk]; bi = kk; }
            bi2[hf] = bi;
            float e[8], ss = 0.f;
            #pragma unroll
            for (int kk = 0; kk < 8; kk++) { e[kk] = __expf(lg[kk] - mx); ss += e[kk]; }
            float rs = 1.0f / ss;

            if (c4l == 0 && grow < B) {
                o_idx[grow] = (float)bi;
                *(float4*)&o_soft[(size_t)grow * 8]     = make_float4(e[0]*rs, e[1]*rs, e[2]*rs, e[3]*rs);
                *(float4*)&o_soft[(size_t)grow * 8 + 4] = make_float4(e[4]*rs, e[5]*rs, e[6]*rs, e[7]*rs);
                *(float4*)&o_log [(size_t)grow * 8]     = make_float4(lg[0], lg[1], lg[2], lg[3]);
                *(float4*)&o_log [(size_t)grow * 8 + 4] = make_float4(lg[4], lg[5], lg[6], lg[7]);
            }
        }

        // ---- embedding write: warp-local, coalesced 512 B per row ----
        #pragma unroll 1
        for (int r = 0; r < 16; r++) {
            int bsrc = __shfl_sync(0xffffffffu, (r >= 8) ? bi2[1] : bi2[0], (r & 7) * 4);
            int grow = t * TM + warp * 16 + r;
            if (grow < B) {
                float4 v = *(const float4*)(sm + OFF_SCB + ((size_t)bsrc * 132 + lane * 4) * 4);
                *(float4*)&o_emb[(size_t)grow * 128 + lane * 4] = v;
            }
        }
    }
}

extern "C" void kernel_launch(void* const* d_in, const int* in_sizes, int n_in,
                              void* d_out, int out_size) {
    const float* x  = (const float*)d_in[0];
    const float* W  = (const float*)d_in[1];
    const float* b  = (const float*)d_in[2];
    const float* g  = (const float*)d_in[3];
    const float* be = (const float*)d_in[4];
    const float* cb = (const float*)d_in[5];

    int B = in_sizes[0] / D_;
    float* out    = (float*)d_out;
    float* o_idx  = out;
    float* o_soft = out + (size_t)B;
    float* o_emb  = o_soft + (size_t)B * 8;
    float* o_log  = o_emb + (size_t)B * 128;

    int NT = (B + TM - 1) / TM;
    int sms = 148;
    cudaDeviceGetAttribute(&sms, cudaDevAttrMultiProcessorCount, 0);
    int grid = (NT < sms) ? NT : sms;

    cudaFuncSetAttribute(l1q_mma, cudaFuncAttributeMaxDynamicSharedMemorySize, SMEM_TOTAL);
    l1q_mma<<<grid, NTH, SMEM_TOTAL>>>(x, W, b, g, be, cb,
                                       o_idx, o_soft, o_emb, o_log, B, NT, grid);
}

// round 16
// speedup vs baseline: 1.0501x; 1.0501x over previous
#include <cuda_runtime.h>
#include <cuda_fp16.h>
#include <cstdint>

#define D_ 128
#define TM 128
#define NTH 256
#define XSCALE 1024.0f
#define WSCALE 256.0f
#define INV_SC 3.814697265625e-06f   // 2^-18

// smem layout (bytes) — x never touches smem
#define WB 36992                      // 136 n-rows * 272 B
#define OFF_W1 0
#define OFF_W2 WB
#define OFF_SB  (2*WB)                // 73984
#define OFF_SG  (OFF_SB + 512)
#define OFF_SBE (OFF_SG + 512)
#define OFF_GBE (OFF_SBE + 512)       // 64 float4: {g[2i],g[2i+1],be[2i],be[2i+1]}
#define OFF_SCB (OFF_GBE + 1024)      // 8 * 132 * 4 = 4224
#define OFF_GK  (OFF_SCB + 4224)
#define OFF_BBK (OFF_GK + 32)
#define OFF_BDK (OFF_BBK + 32)
#define OFF_SCI (OFF_BDK + 32)
#define SMEM_TOTAL (OFF_SCI + 32)

__device__ __forceinline__ uint32_t s2u(const void* p) {
    uint32_t a;
    asm("{ .reg .u64 t; cvta.to.shared.u64 t, %1; cvt.u32.u64 %0, t; }" : "=r"(a) : "l"(p));
    return a;
}
__device__ __forceinline__ uint32_t f2h2(float lo, float hi) {
    uint32_t d;
    asm("cvt.rn.f16x2.f32 %0, %1, %2;" : "=r"(d) : "f"(hi), "f"(lo));
    return d;
}
__device__ __forceinline__ float2 h2f2(uint32_t h) {
    float2 r;
    asm("{ .reg .b16 l, hh; mov.b32 {l, hh}, %2; cvt.f32.f16 %0, l; cvt.f32.f16 %1, hh; }"
        : "=f"(r.x), "=f"(r.y) : "r"(h));
    return r;
}
__device__ __forceinline__ void split2(float a, float b, uint32_t& hi, uint32_t& lo) {
    hi = f2h2(a, b);
    float2 f = h2f2(hi);
    lo = f2h2(a - f.x, b - f.y);
}
__device__ __forceinline__ void ldmx4(uint32_t* r, uint32_t addr) {
    asm volatile("ldmatrix.sync.aligned.m8n8.x4.shared.b16 {%0,%1,%2,%3}, [%4];"
                 : "=r"(r[0]), "=r"(r[1]), "=r"(r[2]), "=r"(r[3]) : "r"(addr));
}
__device__ __forceinline__ void mma16816(float4& c, const uint32_t* a, uint32_t b0, uint32_t b1) {
    asm volatile("mma.sync.aligned.m16n8k16.row.col.f32.f16.f16.f32 "
                 "{%0,%1,%2,%3},{%4,%5,%6,%7},{%8,%9},{%0,%1,%2,%3};"
                 : "+f"(c.x), "+f"(c.y), "+f"(c.z), "+f"(c.w)
                 : "r"(a[0]), "r"(a[1]), "r"(a[2]), "r"(a[3]), "r"(b0), "r"(b1));
}

__global__ void __launch_bounds__(NTH, 2)
l1q_mma(const float* __restrict__ x, const float* __restrict__ W,
        const float* __restrict__ bias, const float* __restrict__ gamma,
        const float* __restrict__ beta, const float* __restrict__ cb,
        float* __restrict__ o_idx, float* __restrict__ o_soft,
        float* __restrict__ o_emb, float* __restrict__ o_log,
        int B, int NT, int grid)
{
    extern __shared__ char sm[];
    const uint32_t base = s2u(sm);
    const int tid = threadIdx.x;
    const int lane = tid & 31;
    const int warp = tid >> 5;

    float* sb  = (float*)(sm + OFF_SB);
    float* sg  = (float*)(sm + OFF_SG);
    float* sbe = (float*)(sm + OFF_SBE);
    float* scb = (float*)(sm + OFF_SCB);
    float* gk  = (float*)(sm + OFF_GK);
    float* bbk = (float*)(sm + OFF_BBK);
    float* bdk = (float*)(sm + OFF_BDK);
    float* sci = (float*)(sm + OFF_SCI);

    // ---- stage W (scaled x256, fp16 hi/lo split) as [n][k], stride 272 B ----
    #pragma unroll 1
    for (int q2 = tid; q2 < 8192; q2 += NTH) {
        int n = q2 >> 6, kp = q2 & 63;
        float2 v = *(const float2*)&W[(size_t)n * 128 + 2 * kp];
        v.x *= WSCALE; v.y *= WSCALE;
        uint32_t hi, lo; split2(v.x, v.y, hi, lo);
        uint32_t off = (uint32_t)n * 272 + (uint32_t)kp * 4;
        *(uint32_t*)(sm + OFF_W1 + off) = hi;
        *(uint32_t*)(sm + OFF_W2 + off) = lo;
    }
    if (tid < 128) { sb[tid] = bias[tid]; sg[tid] = gamma[tid]; sbe[tid] = beta[tid]; }
    #pragma unroll 1
    for (int i = tid; i < 1024; i += NTH) { int k = i >> 7, j = i & 127; scb[k * 132 + j] = cb[i]; }
    __syncthreads();
    if (tid < 64) {
        float4 gb;
        gb.x = sg[2 * tid]; gb.y = sg[2 * tid + 1];
        gb.z = sbe[2 * tid]; gb.w = sbe[2 * tid + 1];
        *(float4*)(sm + OFF_GBE + tid * 16) = gb;
    }

    // ---- ck'' = W^T (gamma o c_k) appended as B-rows 128..135 ----
    if (tid < 128) {
        int d = tid;
        float a8[8] = {0, 0, 0, 0, 0, 0, 0, 0};
        #pragma unroll 4
        for (int j = 0; j < 128; j++) {
            float tj = W[(size_t)j * 128 + d] * sg[j];
            #pragma unroll
            for (int k = 0; k < 8; k++) a8[k] = fmaf(tj, scb[k * 132 + j], a8[k]);
        }
        #pragma unroll
        for (int k = 0; k < 8; k++) {
            float vs = a8[k] * WSCALE;
            __half h1 = __float2half_rn(vs);
            __half h2 = __float2half_rn(vs - __half2float(h1));
            uint32_t off = (uint32_t)(128 + k) * 272 + (uint32_t)d * 2;
            *(__half*)(sm + OFF_W1 + off) = h1;
            *(__half*)(sm + OFF_W2 + off) = h2;
        }
    }
    if (tid < 8) {
        int k = tid; float g = 0, bb = 0, bd = 0, s2 = 0;
        for (int j = 0; j < 128; j++) {
            float c = scb[k * 132 + j], gj = sg[j];
            g  = fmaf(gj, c, g);
            bb = fmaf(sbe[j], c, bb);
            bd = fmaf(sb[j] * gj, c, bd);
            s2 = fmaf(c, c, s2);
        }
        gk[k] = g; bbk[k] = bb; bdk[k] = bd;
        sci[k] = 1.0f / fmaxf(sqrtf(s2), 1e-12f);
    }
    __syncthreads();
    // From here: smem is read-only; no block barriers in the main loop.

    const int g4 = lane >> 2, c4l = lane & 3;
    const uint32_t boff = (uint32_t)(lane & 7) * 272 + (uint32_t)(lane >> 3) * 16;
    const int rbase = warp * 16 + g4;

    // raw x fragment staging (global -> regs, single-buffer, distance-1 prefetch)
    float2 P[8];
    auto ldkp = [&](const float* p0, const float* p1, int kp) {
        int b0 = kp * 32 + 2 * c4l;
        P[0] = *(const float2*)(p0 + b0);
        P[1] = *(const float2*)(p1 + b0);
        P[2] = *(const float2*)(p0 + b0 + 8);
        P[3] = *(const float2*)(p1 + b0 + 8);
        P[4] = *(const float2*)(p0 + b0 + 16);
        P[5] = *(const float2*)(p1 + b0 + 16);
        P[6] = *(const float2*)(p0 + b0 + 24);
        P[7] = *(const float2*)(p1 + b0 + 24);
    };
    auto rowptr = [&](int t_, int add) -> const float* {
        long r = (long)t_ * TM + rbase + add;
        if (r > (long)B - 1) r = B - 1;
        return x + (size_t)r * D_;
    };

    int t0 = blockIdx.x;
    const float* pr0 = rowptr(t0 < NT ? t0 : 0, 0);
    const float* pr1 = rowptr(t0 < NT ? t0 : 0, 8);
    if (t0 < NT) ldkp(pr0, pr1, 0);

    for (int t = t0; t < NT; t += grid) {
        int tn = t + grid;
        const float* nr0 = (tn < NT) ? rowptr(tn, 0) : pr0;
        const float* nr1 = (tn < NT) ? rowptr(tn, 8) : pr1;

        // ---- MMA: warp's 16 rows x N=136 (17 n-tiles), K=128, 3 passes ----
        float4 acc[17];
        #pragma unroll
        for (int j = 0; j < 17; j++) acc[j] = make_float4(0.f, 0.f, 0.f, 0.f);

        #pragma unroll
        for (int kp = 0; kp < 4; kp++) {
            uint32_t ah[2][4], al[2][4];
            #pragma unroll
            for (int kk = 0; kk < 2; kk++)
                #pragma unroll
                for (int v = 0; v < 4; v++)
                    split2(P[kk * 4 + v].x * XSCALE, P[kk * 4 + v].y * XSCALE,
                           ah[kk][v], al[kk][v]);
            // prefetch next kp of this tile, or kp0 of next tile
            if (kp < 3) ldkp(pr0, pr1, kp + 1);
            else        ldkp(nr0, nr1, 0);

            uint32_t wk = base + boff + (uint32_t)kp * 64;
            // pair-interleaved j: dependency distance 2 on each acc register
            #pragma unroll
            for (int jp = 0; jp < 8; jp++) {
                int j0 = 2 * jp, j1 = 2 * jp + 1;
                uint32_t wa0 = wk + (uint32_t)j0 * (8 * 272);
                uint32_t wa1 = wk + (uint32_t)j1 * (8 * 272);
                uint32_t bh0[4], bl0[4], bh1[4], bl1[4];
                ldmx4(bh0, wa0 + OFF_W1);
                ldmx4(bh1, wa1 + OFF_W1);
                ldmx4(bl0, wa0 + OFF_W2);
                ldmx4(bl1, wa1 + OFF_W2);
                mma16816(acc[j0], ah[0], bh0[0], bh0[1]);
                mma16816(acc[j1], ah[0], bh1[0], bh1[1]);
                mma16816(acc[j0], ah[0], bl0[0], bl0[1]);
                mma16816(acc[j1], ah[0], bl1[0], bl1[1]);
                mma16816(acc[j0], al[0], bh0[0], bh0[1]);
                mma16816(acc[j1], al[0], bh1[0], bh1[1]);
                mma16816(acc[j0], ah[1], bh0[2], bh0[3]);
                mma16816(acc[j1], ah[1], bh1[2], bh1[3]);
                mma16816(acc[j0], ah[1], bl0[2], bl0[3]);
                mma16816(acc[j1], ah[1], bl1[2], bl1[3]);
                mma16816(acc[j0], al[1], bh0[2], bh0[3]);
                mma16816(acc[j1], al[1], bh1[2], bh1[3]);
            }
            {   // j = 16 singleton (logits columns)
                uint32_t wa = wk + (uint32_t)16 * (8 * 272);
                uint32_t bh[4], bl[4];
                ldmx4(bh, wa + OFF_W1);
                ldmx4(bl, wa + OFF_W2);
                mma16816(acc[16], ah[0], bh[0], bh[1]);
                mma16816(acc[16], ah[0], bl[0], bl[1]);
                mma16816(acc[16], al[0], bh[0], bh[1]);
                mma16816(acc[16], ah[1], bh[2], bh[3]);
                mma16816(acc[16], ah[1], bl[2], bl[3]);
                mma16816(acc[16], al[1], bh[2], bh[3]);
            }
        }
        pr0 = nr0; pr1 = nr1;

        // ---- fused epilogue: both half-rows together, h overwrites acc ----
        float s1a = 0.f, s2a = 0.f, s1b = 0.f, s2b = 0.f;
        #pragma unroll
        for (int j = 0; j < 16; j++) {
            float2 bb = *(const float2*)(sm + OFF_SB + (8 * j + 2 * c4l) * 4);
            float h0 = fmaf(acc[j].x, INV_SC, bb.x);
            float h1 = fmaf(acc[j].y, INV_SC, bb.y);
            float h2 = fmaf(acc[j].z, INV_SC, bb.x);
            float h3 = fmaf(acc[j].w, INV_SC, bb.y);
            acc[j] = make_float4(h0, h1, h2, h3);
            s1a += h0 + h1; s2a = fmaf(h0, h0, fmaf(h1, h1, s2a));
            s1b += h2 + h3; s2b = fmaf(h2, h2, fmaf(h3, h3, s2b));
        }
        s1a += __shfl_xor_sync(0xffffffffu, s1a, 1); s1a += __shfl_xor_sync(0xffffffffu, s1a, 2);
        s2a += __shfl_xor_sync(0xffffffffu, s2a, 1); s2a += __shfl_xor_sync(0xffffffffu, s2a, 2);
        s1b += __shfl_xor_sync(0xffffffffu, s1b, 1); s1b += __shfl_xor_sync(0xffffffffu, s1b, 2);
        s2b += __shfl_xor_sync(0xffffffffu, s2b, 1); s2b += __shfl_xor_sync(0xffffffffu, s2b, 2);
        float mua = s1a * 0.0078125f, mub = s1b * 0.0078125f;
        float rstda = rsqrtf(s2a * 0.0078125f - mua * mua + 1e-5f);
        float rstdb = rsqrtf(s2b * 0.0078125f - mub * mub + 1e-5f);

        float q2a = 0.f, q2b = 0.f;
        #pragma unroll
        for (int j = 0; j < 16; j++) {
            float4 gb = *(const float4*)(sm + OFF_GBE + (4 * j + c4l) * 16);
            float hn0 = fmaf((acc[j].x - mua) * rstda, gb.x, gb.z);
            float hn1 = fmaf((acc[j].y - mua) * rstda, gb.y, gb.w);
            float hn2 = fmaf((acc[j].z - mub) * rstdb, gb.x, gb.z);
            float hn3 = fmaf((acc[j].w - mub) * rstdb, gb.y, gb.w);
            q2a = fmaf(hn0, hn0, fmaf(hn1, hn1, q2a));
            q2b = fmaf(hn2, hn2, fmaf(hn3, hn3, q2b));
        }
        q2a += __shfl_xor_sync(0xffffffffu, q2a, 1); q2a += __shfl_xor_sync(0xffffffffu, q2a, 2);
        q2b += __shfl_xor_sync(0xffffffffu, q2b, 1); q2b += __shfl_xor_sync(0xffffffffu, q2b, 2);
        float invna = 1.0f / fmaxf(sqrtf(q2a), 1e-12f);
        float invnb = 1.0f / fmaxf(sqrtf(q2b), 1e-12f);

        float bd0 = bdk[2 * c4l], bd1 = bdk[2 * c4l + 1];
        float gk0 = gk[2 * c4l],  gk1 = gk[2 * c4l + 1];
        float bk0 = bbk[2 * c4l], bk1 = bbk[2 * c4l + 1];
        float sc0 = sci[2 * c4l], sc1 = sci[2 * c4l + 1];
        float l0a = fmaf(rstda, fmaf(acc[16].x, INV_SC, bd0) - mua * gk0, bk0) * invna * sc0;
        float l1a = fmaf(rstda, fmaf(acc[16].y, INV_SC, bd1) - mua * gk1, bk1) * invna * sc1;
        float l0b = fmaf(rstdb, fmaf(acc[16].z, INV_SC, bd0) - mub * gk0, bk0) * invnb * sc0;
        float l1b = fmaf(rstdb, fmaf(acc[16].w, INV_SC, bd1) - mub * gk1, bk1) * invnb * sc1;

        int bi2[2];
        #pragma unroll 1
        for (int hf = 0; hf < 2; hf++) {
            float l0 = hf ? l0b : l0a, l1 = hf ? l1b : l1a;
            int grow = t * TM + warp * 16 + hf * 8 + g4;

            float lg[8];
            #pragma unroll
            for (int kk = 0; kk < 8; kk++) {
                int src = (lane & ~3) | (kk >> 1);
                lg[kk] = __shfl_sync(0xffffffffu, (kk & 1) ? l1 : l0, src);
            }
            float mx = lg[0]; int bi = 0;
            #pragma unroll
            for (int kk = 1; kk < 8; kk++) if (lg[kk] > mx) { mx = lg[kk]; bi = kk; }
            bi2[hf] = bi;
            float e[8], ss = 0.f;
            #pragma unroll
            for (int kk = 0; kk < 8; kk++) { e[kk] = __expf(lg[kk] - mx); ss += e[kk]; }
            float rs = 1.0f / ss;

            if (c4l == 0 && grow < B) {
                o_idx[grow] = (float)bi;
                *(float4*)&o_soft[(size_t)grow * 8]     = make_float4(e[0]*rs, e[1]*rs, e[2]*rs, e[3]*rs);
                *(float4*)&o_soft[(size_t)grow * 8 + 4] = make_float4(e[4]*rs, e[5]*rs, e[6]*rs, e[7]*rs);
                *(float4*)&o_log [(size_t)grow * 8]     = make_float4(lg[0], lg[1], lg[2], lg[3]);
                *(float4*)&o_log [(size_t)grow * 8 + 4] = make_float4(lg[4], lg[5], lg[6], lg[7]);
            }
        }

        // ---- embedding write: warp-local, coalesced 512 B per row ----
        #pragma unroll 1
        for (int r = 0; r < 16; r++) {
            int bsrc = __shfl_sync(0xffffffffu, (r >= 8) ? bi2[1] : bi2[0], (r & 7) * 4);
            int grow = t * TM + warp * 16 + r;
            if (grow < B) {
                float4 v = *(const float4*)(sm + OFF_SCB + ((size_t)bsrc * 132 + lane * 4) * 4);
                *(float4*)&o_emb[(size_t)grow * 128 + lane * 4] = v;
            }
        }
    }
}

extern "C" void kernel_launch(void* const* d_in, const int* in_sizes, int n_in,
                              void* d_out, int out_size) {
    const float* x  = (const float*)d_in[0];
    const float* W  = (const float*)d_in[1];
    const float* b  = (const float*)d_in[2];
    const float* g  = (const float*)d_in[3];
    const float* be = (const float*)d_in[4];
    const float* cb = (const float*)d_in[5];

    int B = in_sizes[0] / D_;
    float* out    = (float*)d_out;
    float* o_idx  = out;
    float* o_soft = out + (size_t)B;
    float* o_emb  = o_soft + (size_t)B * 8;
    float* o_log  = o_emb + (size_t)B * 128;

    int NT = (B + TM - 1) / TM;
    int sms = 148;
    cudaDeviceGetAttribute(&sms, cudaDevAttrMultiProcessorCount, 0);
    int grid = (NT < 2 * sms) ? NT : 2 * sms;

    cudaFuncSetAttribute(l1q_mma, cudaFuncAttributeMaxDynamicSharedMemorySize, SMEM_TOTAL);
    l1q_mma<<<grid, NTH, SMEM_TOTAL>>>(x, W, b, g, be, cb,
                                       o_idx, o_soft, o_emb, o_log, B, NT, grid);
}